// round 13
// baseline (speedup 1.0000x reference)
#include <cuda_runtime.h>

#define B_   32
#define S_   1024
#define ATT_ 512
#define W_   8
#define MONO_S_ 384   // energies precomputed for s < MONO_S_
#define MONO_TILES_ 12
#define PF_BLOCKS_ 96 // value-prefetch blocks piggybacked on k_scan

// ---------------- scratch (no allocations allowed) ----------------
__device__ float g_qbm[B_ * ATT_];   // dec_h @ Wm^T + bm
__device__ float g_qbc[B_ * ATT_];   // dec_h @ Wc^T + bc
__device__ float g_vnm[ATT_];        // gm * vm / ||vm||
__device__ float g_vnc[ATT_];
__device__ float g_me[B_ * S_];      // monotonic energy (s < MONO_S_)
__device__ float g_ce[B_ * S_];      // chunk energy    (s < MONO_S_)
__device__ float g_beta[B_ * S_];
__device__ int   g_cut[B_];          // per-batch active cutoff (inclusive)
__device__ float g_sink;             // never-written-in-practice sink

__device__ __forceinline__ float tanha(float x) {
    float y;
    asm("tanh.approx.f32 %0, %1;" : "=f"(y) : "f"(x));
    return y;
}

// ---------------- K0: matvec + vnorm + zero (fused pre-pass) ------
__global__ void __launch_bounds__(256) k_pre(
        const float* __restrict__ dec,
        const float* __restrict__ Wm, const float* __restrict__ bm,
        const float* __restrict__ Wc, const float* __restrict__ bc,
        const float* __restrict__ vm, const float* __restrict__ gm,
        const float* __restrict__ vc, const float* __restrict__ gc,
        float* __restrict__ out) {
    int t = threadIdx.x;

    if (blockIdx.y == 2) {
        int x = blockIdx.x;
        out[x * 512 + t] = 0.f;
        out[x * 512 + 256 + t] = 0.f;
        if (x > 1) return;
        const float* v = x ? vc : vm;
        const float* g = x ? gc : gm;
        float* o       = x ? g_vnc : g_vnm;
        float x1 = v[t], x2 = v[t + 256];
        float ss = x1 * x1 + x2 * x2;
        __shared__ float red[8];
        #pragma unroll
        for (int off = 16; off; off >>= 1) ss += __shfl_down_sync(0xffffffffu, ss, off);
        if ((t & 31) == 0) red[t >> 5] = ss;
        __syncthreads();
        __shared__ float s_scale;
        if (t == 0) {
            float a = red[0] + red[1] + red[2] + red[3] + red[4] + red[5] + red[6] + red[7];
            s_scale = __ldg(g) / sqrtf(a);
        }
        __syncthreads();
        o[t] = x1 * s_scale;
        o[t + 256] = x2 * s_scale;
        return;
    }

    const float* W    = blockIdx.y ? Wc : Wm;
    const float* bias = blockIdx.y ? bc : bm;
    float* qout       = blockIdx.y ? g_qbc : g_qbm;

    int w = t >> 5, lane = t & 31;
    int row0 = blockIdx.x * 16 + w * 2;          // 2 rows per warp

    const float4* W40 = reinterpret_cast<const float4*>(W + (size_t)row0 * 512);
    const float4* W41 = reinterpret_cast<const float4*>(W + (size_t)(row0 + 1) * 512);
    float4 w0[4], w1[4];
    #pragma unroll
    for (int j = 0; j < 4; j++) { w0[j] = W40[lane + 32 * j]; w1[j] = W41[lane + 32 * j]; }
    float bias0 = bias[row0], bias1 = bias[row0 + 1];

    __shared__ float4 sdec[16 * 128];            // 32 KB: 16 batches
    const float4* dec4 = reinterpret_cast<const float4*>(dec);

    #pragma unroll
    for (int half = 0; half < 2; half++) {
        #pragma unroll
        for (int i = t; i < 2048; i += 256) sdec[i] = dec4[half * 2048 + i];
        __syncthreads();
        #pragma unroll 4
        for (int bb = 0; bb < 16; bb++) {
            int b = half * 16 + bb;
            float a0 = 0.f, a1 = 0.f;
            #pragma unroll
            for (int j = 0; j < 4; j++) {
                float4 dv = sdec[bb * 128 + lane + 32 * j];
                a0 += w0[j].x * dv.x + w0[j].y * dv.y + w0[j].z * dv.z + w0[j].w * dv.w;
                a1 += w1[j].x * dv.x + w1[j].y * dv.y + w1[j].z * dv.z + w1[j].w * dv.w;
            }
            #pragma unroll
            for (int off = 16; off; off >>= 1) {
                a0 += __shfl_down_sync(0xffffffffu, a0, off);
                a1 += __shfl_down_sync(0xffffffffu, a1, off);
            }
            if (lane == 0) {
                qout[b * ATT_ + row0]     = a0 + bias0;
                qout[b * ATT_ + row0 + 1] = a1 + bias1;
            }
        }
        __syncthreads();
    }
}

// ---------------- K1: both energies for s < MONO_S_ (one key pass) -
__global__ void __launch_bounds__(256) k_both(
        const float* __restrict__ key,
        const float* __restrict__ vbm, const float* __restrict__ rm,
        const float* __restrict__ vbc, const float* __restrict__ rc) {
    int b = blockIdx.y;
    int tile = blockIdx.x;
    int t = threadIdx.x, w = t >> 5, lane = t & 31;

    __shared__ float sq[2048];   // [qm 512 | qc 512 | vm 512 | vc 512]
    {
        const float4* qm4 = reinterpret_cast<const float4*>(g_qbm + b * ATT_);
        const float4* qc4 = reinterpret_cast<const float4*>(g_qbc + b * ATT_);
        const float4* vm4 = reinterpret_cast<const float4*>(g_vnm);
        const float4* vc4 = reinterpret_cast<const float4*>(g_vnc);
        float4* s4 = reinterpret_cast<float4*>(sq);
        if (t < 128) {
            s4[t]       = qm4[t];
            s4[256 + t] = vm4[t];
        } else {
            int u = t - 128;
            s4[128 + u] = qc4[u];
            s4[384 + u] = vc4[u];
        }
    }
    __syncthreads();

    const float cm = __ldg(vbm) + __ldg(rm);
    const float cc = __ldg(vbc) + __ldg(rc);

    int s0 = tile * 32 + w * 4;
    #pragma unroll
    for (int r = 0; r < 4; r++) {
        int s = s0 + r;
        const float* kp = key + (((size_t)b * S_ + s) << 9);
        float kv[16];
        #pragma unroll
        for (int j = 0; j < 16; j++) kv[j] = kp[lane + 32 * j];
        float em = 0.f, ec = 0.f;
        #pragma unroll
        for (int j = 0; j < 16; j++) {
            int idx = lane + 32 * j;
            em += sq[1024 + idx] * tanha(sq[idx] + kv[j]);
            ec += sq[1536 + idx] * tanha(sq[512 + idx] + kv[j]);
        }
        #pragma unroll
        for (int off = 16; off; off >>= 1) {
            em += __shfl_down_sync(0xffffffffu, em, off);
            ec += __shfl_down_sync(0xffffffffu, ec, off);
        }
        if (lane == 0) {
            g_me[b * S_ + s] = em + cm;
            g_ce[b * S_ + s] = ec + cc;
        }
    }
}

// ---------------- K2: fused cutoff + scans -> beta  (+ L2 staging) -
// Blocks [0,32): per-batch scan (as in R12).  Blocks [32,128): stream
// the live value region (24 MB) through L2 with REAL loads, hidden
// under the scan's latency chain, so k_ctx hits L2 instead of DRAM.
__global__ void __launch_bounds__(1024) k_scan(
        const float* __restrict__ noise, const float* __restrict__ prev,
        const float* __restrict__ key, const float* __restrict__ value,
        const float* __restrict__ vbm, const float* __restrict__ rm,
        const float* __restrict__ vbc, const float* __restrict__ rc) {
    int s = threadIdx.x;

    if (blockIdx.x >= B_) {               // ---- value L2-staging blocks
        int pid = blockIdx.x - B_;        // 0..PF_BLOCKS_-1
        const int span = MONO_S_ * 512;   // 196608 floats per batch
        const int nthr = PF_BLOCKS_ * 1024;
        float acc = 0.f;
        #pragma unroll 4
        for (int b2 = 0; b2 < B_; b2++) {
            const float* vb = value + (size_t)b2 * (S_ * 512);
            for (int i = pid * 1024 + s; i < span; i += nthr)
                acc += vb[i];
        }
        if (__float_as_uint(acc) == 0xdeadbeefu) g_sink = acc;  // keep loads live
        return;
    }

    int b = blockIdx.x;
    int lane = s & 31, wid = s >> 5;
    const int base = b * S_;
    __shared__ float smA[S_];
    __shared__ float smC[S_];
    __shared__ float wa[32], wb[32], wc[32];
    __shared__ int   s_wf[MONO_TILES_];
    __shared__ float s_psum;

    bool head = (s < MONO_S_);
    float e  = head ? g_me[base + s] : 0.f;
    float c  = head ? g_ce[base + s] : 0.f;
    float nz = noise[base + s];
    float pv = prev[base + s];

    float p = 1.f / (1.f + __expf(-(e + nz)));
    float omp = head ? (1.f - p) : 1.f;

    float x = omp;
    #pragma unroll
    for (int o = 1; o < 32; o <<= 1) {
        float y = __shfl_up_sync(0xffffffffu, x, o);
        if (lane >= o) x *= y;
    }
    if (lane == 31) wa[wid] = x;
    float ts = pv;
    #pragma unroll
    for (int off = 16; off; off >>= 1) ts += __shfl_down_sync(0xffffffffu, ts, off);
    if (lane == 0) wb[wid] = ts;
    __syncthreads();                                        // B1

    if (wid == 0) {
        float a = wa[lane];
        #pragma unroll
        for (int o = 1; o < 32; o <<= 1) {
            float y = __shfl_up_sync(0xffffffffu, a, o);
            if (lane >= o) a *= y;
        }
        wa[lane] = a;
    } else if (wid == 1) {
        float a = wb[lane];
        #pragma unroll
        for (int off = 16; off; off >>= 1) a += __shfl_down_sync(0xffffffffu, a, off);
        if (lane == 0) s_psum = a;
    }
    __syncthreads();                                        // B2

    float ip = wid ? x * wa[wid - 1] : x;
    unsigned zb = __ballot_sync(0xffffffffu, ip == 0.f);
    if (wid < MONO_TILES_ && lane == 0)
        s_wf[wid] = zb ? (wid * 32 + __ffs(zb) - 1) : 0x7fffffff;
    smA[s] = ip;
    __syncthreads();                                        // B3

    int Z = 0x7fffffff;
    #pragma unroll
    for (int i = 0; i < MONO_TILES_; i++) Z = min(Z, s_wf[i]);
    const int cut = (Z <= MONO_S_ - 33) ? Z + 32 : 1024;
    if (s == 0) g_cut[b] = cut;

    if (cut >= 1024) {
        // rare fallback: compute tail energies, redo the product scan
        if (!head) {
            const float cm = __ldg(vbm) + __ldg(rm);
            const float cc = __ldg(vbc) + __ldg(rc);
            const float* kp = key + (((size_t)base + s) << 9);
            const float* qm = g_qbm + b * ATT_;
            const float* qc = g_qbc + b * ATT_;
            float em = 0.f, ec = 0.f;
            for (int j = 0; j < ATT_; j++) {
                float kvj = kp[j];
                em += g_vnm[j] * tanha(qm[j] + kvj);
                ec += g_vnc[j] * tanha(qc[j] + kvj);
            }
            e = em + cm;
            c = ec + cc;
            p = 1.f / (1.f + __expf(-(e + nz)));
        }
        if (s == S_ - 1) p = 1.f;
        omp = 1.f - p;
        float x2f = omp;
        #pragma unroll
        for (int o = 1; o < 32; o <<= 1) {
            float y = __shfl_up_sync(0xffffffffu, x2f, o);
            if (lane >= o) x2f *= y;
        }
        if (lane == 31) wa[wid] = x2f;
        __syncthreads();
        if (wid == 0) {
            float a = wa[lane];
            #pragma unroll
            for (int o = 1; o < 32; o <<= 1) {
                float y = __shfl_up_sync(0xffffffffu, a, o);
                if (lane >= o) a *= y;
            }
            wa[lane] = a;
        }
        __syncthreads();
        float ip2 = wid ? x2f * wa[wid - 1] : x2f;
        smA[s] = ip2;
        __syncthreads();
    }

    const bool dead = (s > cut);
    smC[s] = c;

    float cp = s ? smA[s - 1] : 1.f;       // dead lanes: cp == 0 exactly
    float cpc = fminf(fmaxf(cp, 1e-20f), 1.f);
    float y2 = dead ? 0.f : (pv / s_psum) / cpc;

    float xs = y2;
    #pragma unroll
    for (int o = 1; o < 32; o <<= 1) {
        float y = __shfl_up_sync(0xffffffffu, xs, o);
        if (lane >= o) xs += y;
    }
    if (lane == 31) wc[wid] = xs;
    __syncthreads();                                        // B4
    if (wid == 0) {
        float a = wc[lane];
        #pragma unroll
        for (int o = 1; o < 32; o <<= 1) {
            float y = __shfl_up_sync(0xffffffffu, a, o);
            if (lane >= o) a += y;
        }
        wc[lane] = a;
    }
    __syncthreads();                                        // B5
    float cs = wid ? xs + wc[wid - 1] : xs;
    float alpha = p * cp * cs;              // dead -> p*0*cs = 0 exactly

    float mx = c;
    #pragma unroll
    for (int j = 1; j < W_; j++) { int i = s - j; if (i >= 0) mx = fmaxf(mx, smC[i]); }
    float eu = __expf(c - mx);              // <= 1, never inf
    smA[s] = eu;
    __syncthreads();                                        // B6

    float den = 0.f;
    #pragma unroll
    for (int j = 0; j < W_; j++) { int i = s - j; if (i >= 0) den += smA[i]; }
    den = fmaxf(den, 1e-10f);
    float g = dead ? 0.f : alpha / den;
    smC[s] = g;
    __syncthreads();                                        // B7

    float acc = 0.f;
    #pragma unroll
    for (int j = 0; j < W_; j++) { int i = s + j; if (i < S_) acc += smC[i]; }
    g_beta[base + s] = dead ? 0.f : eu * acc;
}

// ---------------- K3: context = beta . value (L2-warm) -------------
#define SCHUNK_ 16
#define NCHUNK_LIVE_ 24
__global__ void __launch_bounds__(256) k_ctx(const float* __restrict__ value,
                                             float* __restrict__ out) {
    int b = blockIdx.y;
    int cut = g_cut[b];
    int t = threadIdx.x;
    __shared__ float sb[SCHUNK_];

    for (int sc = blockIdx.x; sc < S_ / SCHUNK_; sc += NCHUNK_LIVE_) {
        if (sc * SCHUNK_ > cut) return;      // beta exactly 0 beyond cut
        if (t < SCHUNK_) sb[t] = g_beta[b * S_ + sc * SCHUNK_ + t];
        __syncthreads();
        const float* vp = value + (((size_t)b * S_ + sc * SCHUNK_) << 9);
        float a0 = 0.f, a1 = 0.f;
        #pragma unroll
        for (int s = 0; s < SCHUNK_; s++) {
            float bs = sb[s];
            a0 += bs * vp[(s << 9) + t];
            a1 += bs * vp[(s << 9) + t + 256];
        }
        atomicAdd(out + b * 512 + t,       a0);
        atomicAdd(out + b * 512 + t + 256, a1);
        __syncthreads();
    }
}

// ---------------- launch ------------------------------------------
extern "C" void kernel_launch(void* const* d_in, const int* in_sizes, int n_in,
                              void* d_out, int out_size) {
    const float* dec   = (const float*)d_in[0];
    const float* key   = (const float*)d_in[1];
    const float* value = (const float*)d_in[2];
    const float* prev  = (const float*)d_in[3];
    const float* noise = (const float*)d_in[4];
    const float* Wm    = (const float*)d_in[5];
    const float* bm    = (const float*)d_in[6];
    const float* vm    = (const float*)d_in[7];
    const float* gm    = (const float*)d_in[8];
    const float* vbm   = (const float*)d_in[9];
    const float* rm    = (const float*)d_in[10];
    const float* Wc    = (const float*)d_in[11];
    const float* bc    = (const float*)d_in[12];
    const float* vc    = (const float*)d_in[13];
    const float* gc    = (const float*)d_in[14];
    const float* vbc   = (const float*)d_in[15];
    const float* rc    = (const float*)d_in[16];
    float* out = (float*)d_out;

    k_pre<<<dim3(32, 3), 256>>>(dec, Wm, bm, Wc, bc, vm, gm, vc, gc, out);
    k_both<<<dim3(MONO_TILES_, B_), 256>>>(key, vbm, rm, vbc, rc);
    k_scan<<<B_ + PF_BLOCKS_, S_>>>(noise, prev, key, value, vbm, rm, vbc, rc);
    k_ctx<<<dim3(NCHUNK_LIVE_, B_), 256>>>(value, out);
}

// round 14
// speedup vs baseline: 1.3946x; 1.3946x over previous
#include <cuda_runtime.h>

#define B_   32
#define S_   1024
#define ATT_ 512
#define W_   8
#define MONO_S_ 384   // energies precomputed for s < MONO_S_
#define MONO_TILES_ 12

// ---------------- scratch (no allocations allowed) ----------------
__device__ float g_qbm[B_ * ATT_];   // dec_h @ Wm^T + bm
__device__ float g_qbc[B_ * ATT_];   // dec_h @ Wc^T + bc
__device__ float g_vnm[ATT_];        // gm * vm / ||vm||
__device__ float g_vnc[ATT_];
__device__ float g_me[B_ * S_];      // monotonic energy (s < MONO_S_)
__device__ float g_ce[B_ * S_];      // chunk energy    (s < MONO_S_)

__device__ __forceinline__ float tanha(float x) {
    float y;
    asm("tanh.approx.f32 %0, %1;" : "=f"(y) : "f"(x));
    return y;
}

// ---------------- K0: matvec + vnorm (fused pre-pass) -------------
__global__ void __launch_bounds__(256) k_pre(
        const float* __restrict__ dec,
        const float* __restrict__ Wm, const float* __restrict__ bm,
        const float* __restrict__ Wc, const float* __restrict__ bc,
        const float* __restrict__ vm, const float* __restrict__ gm,
        const float* __restrict__ vc, const float* __restrict__ gc) {
    int t = threadIdx.x;

    if (blockIdx.y == 2) {
        int x = blockIdx.x;
        if (x > 1) return;
        const float* v = x ? vc : vm;
        const float* g = x ? gc : gm;
        float* o       = x ? g_vnc : g_vnm;
        float x1 = v[t], x2 = v[t + 256];
        float ss = x1 * x1 + x2 * x2;
        __shared__ float red[8];
        #pragma unroll
        for (int off = 16; off; off >>= 1) ss += __shfl_down_sync(0xffffffffu, ss, off);
        if ((t & 31) == 0) red[t >> 5] = ss;
        __syncthreads();
        __shared__ float s_scale;
        if (t == 0) {
            float a = red[0] + red[1] + red[2] + red[3] + red[4] + red[5] + red[6] + red[7];
            s_scale = __ldg(g) / sqrtf(a);
        }
        __syncthreads();
        o[t] = x1 * s_scale;
        o[t + 256] = x2 * s_scale;
        return;
    }

    const float* W    = blockIdx.y ? Wc : Wm;
    const float* bias = blockIdx.y ? bc : bm;
    float* qout       = blockIdx.y ? g_qbc : g_qbm;

    int w = t >> 5, lane = t & 31;
    int row0 = blockIdx.x * 16 + w * 2;          // 2 rows per warp

    const float4* W40 = reinterpret_cast<const float4*>(W + (size_t)row0 * 512);
    const float4* W41 = reinterpret_cast<const float4*>(W + (size_t)(row0 + 1) * 512);
    float4 w0[4], w1[4];
    #pragma unroll
    for (int j = 0; j < 4; j++) { w0[j] = W40[lane + 32 * j]; w1[j] = W41[lane + 32 * j]; }
    float bias0 = bias[row0], bias1 = bias[row0 + 1];

    __shared__ float4 sdec[16 * 128];            // 32 KB: 16 batches
    const float4* dec4 = reinterpret_cast<const float4*>(dec);

    #pragma unroll
    for (int half = 0; half < 2; half++) {
        #pragma unroll
        for (int i = t; i < 2048; i += 256) sdec[i] = dec4[half * 2048 + i];
        __syncthreads();
        #pragma unroll 4
        for (int bb = 0; bb < 16; bb++) {
            int b = half * 16 + bb;
            float a0 = 0.f, a1 = 0.f;
            #pragma unroll
            for (int j = 0; j < 4; j++) {
                float4 dv = sdec[bb * 128 + lane + 32 * j];
                a0 += w0[j].x * dv.x + w0[j].y * dv.y + w0[j].z * dv.z + w0[j].w * dv.w;
                a1 += w1[j].x * dv.x + w1[j].y * dv.y + w1[j].z * dv.z + w1[j].w * dv.w;
            }
            #pragma unroll
            for (int off = 16; off; off >>= 1) {
                a0 += __shfl_down_sync(0xffffffffu, a0, off);
                a1 += __shfl_down_sync(0xffffffffu, a1, off);
            }
            if (lane == 0) {
                qout[b * ATT_ + row0]     = a0 + bias0;
                qout[b * ATT_ + row0 + 1] = a1 + bias1;
            }
        }
        __syncthreads();
    }
}

// ---------------- K1: both energies for s < MONO_S_ (one key pass) -
__global__ void __launch_bounds__(256) k_both(
        const float* __restrict__ key,
        const float* __restrict__ vbm, const float* __restrict__ rm,
        const float* __restrict__ vbc, const float* __restrict__ rc) {
    int b = blockIdx.y;
    int tile = blockIdx.x;
    int t = threadIdx.x, w = t >> 5, lane = t & 31;

    __shared__ float sq[2048];   // [qm 512 | qc 512 | vm 512 | vc 512]
    {
        const float4* qm4 = reinterpret_cast<const float4*>(g_qbm + b * ATT_);
        const float4* qc4 = reinterpret_cast<const float4*>(g_qbc + b * ATT_);
        const float4* vm4 = reinterpret_cast<const float4*>(g_vnm);
        const float4* vc4 = reinterpret_cast<const float4*>(g_vnc);
        float4* s4 = reinterpret_cast<float4*>(sq);
        if (t < 128) {
            s4[t]       = qm4[t];
            s4[256 + t] = vm4[t];
        } else {
            int u = t - 128;
            s4[128 + u] = qc4[u];
            s4[384 + u] = vc4[u];
        }
    }
    __syncthreads();

    const float cm = __ldg(vbm) + __ldg(rm);
    const float cc = __ldg(vbc) + __ldg(rc);

    int s0 = tile * 32 + w * 4;
    #pragma unroll
    for (int r = 0; r < 4; r++) {
        int s = s0 + r;
        const float* kp = key + (((size_t)b * S_ + s) << 9);
        float kv[16];
        #pragma unroll
        for (int j = 0; j < 16; j++) kv[j] = kp[lane + 32 * j];
        float em = 0.f, ec = 0.f;
        #pragma unroll
        for (int j = 0; j < 16; j++) {
            int idx = lane + 32 * j;
            em += sq[1024 + idx] * tanha(sq[idx] + kv[j]);
            ec += sq[1536 + idx] * tanha(sq[512 + idx] + kv[j]);
        }
        #pragma unroll
        for (int off = 16; off; off >>= 1) {
            em += __shfl_down_sync(0xffffffffu, em, off);
            ec += __shfl_down_sync(0xffffffffu, ec, off);
        }
        if (lane == 0) {
            g_me[b * S_ + s] = em + cm;
            g_ce[b * S_ + s] = ec + cc;
        }
    }
}

// ---------------- K2: cutoff + scans + beta + CONTEXT (fused) ------
// One block per batch. After beta lands in smem, the same block
// computes context = sum_s beta[s] * value[s,:] for its batch and
// writes out directly (no atomics, no g_beta round-trip, no k_ctx).
__global__ void __launch_bounds__(1024) k_scan(
        const float* __restrict__ noise, const float* __restrict__ prev,
        const float* __restrict__ key, const float* __restrict__ value,
        const float* __restrict__ vbm, const float* __restrict__ rm,
        const float* __restrict__ vbc, const float* __restrict__ rc,
        float* __restrict__ out) {
    int b = blockIdx.x, s = threadIdx.x;
    int lane = s & 31, wid = s >> 5;
    const int base = b * S_;
    __shared__ float smA[S_];
    __shared__ float smC[S_];
    __shared__ float wa[32], wb[32], wc[32];
    __shared__ int   s_wf[MONO_TILES_];
    __shared__ float s_psum;

    bool head = (s < MONO_S_);
    float e  = head ? g_me[base + s] : 0.f;
    float c  = head ? g_ce[base + s] : 0.f;
    float nz = noise[base + s];
    float pv = prev[base + s];

    float p = 1.f / (1.f + __expf(-(e + nz)));
    float omp = head ? (1.f - p) : 1.f;

    // product scan (+ prev-sum concurrently)
    float x = omp;
    #pragma unroll
    for (int o = 1; o < 32; o <<= 1) {
        float y = __shfl_up_sync(0xffffffffu, x, o);
        if (lane >= o) x *= y;
    }
    if (lane == 31) wa[wid] = x;
    float ts = pv;
    #pragma unroll
    for (int off = 16; off; off >>= 1) ts += __shfl_down_sync(0xffffffffu, ts, off);
    if (lane == 0) wb[wid] = ts;
    __syncthreads();                                        // B1

    if (wid == 0) {
        float a = wa[lane];
        #pragma unroll
        for (int o = 1; o < 32; o <<= 1) {
            float y = __shfl_up_sync(0xffffffffu, a, o);
            if (lane >= o) a *= y;
        }
        wa[lane] = a;
    } else if (wid == 1) {
        float a = wb[lane];
        #pragma unroll
        for (int off = 16; off; off >>= 1) a += __shfl_down_sync(0xffffffffu, a, off);
        if (lane == 0) s_psum = a;
    }
    __syncthreads();                                        // B2

    float ip = wid ? x * wa[wid - 1] : x;
    unsigned zb = __ballot_sync(0xffffffffu, ip == 0.f);
    if (wid < MONO_TILES_ && lane == 0)
        s_wf[wid] = zb ? (wid * 32 + __ffs(zb) - 1) : 0x7fffffff;
    smA[s] = ip;
    __syncthreads();                                        // B3

    int Z = 0x7fffffff;
    #pragma unroll
    for (int i = 0; i < MONO_TILES_; i++) Z = min(Z, s_wf[i]);
    const int cut = (Z <= MONO_S_ - 33) ? Z + 32 : 1024;

    if (cut >= 1024) {
        // rare fallback: compute tail energies, redo the product scan
        if (!head) {
            const float cm = __ldg(vbm) + __ldg(rm);
            const float cc = __ldg(vbc) + __ldg(rc);
            const float* kp = key + (((size_t)base + s) << 9);
            const float* qm = g_qbm + b * ATT_;
            const float* qc = g_qbc + b * ATT_;
            float em = 0.f, ec = 0.f;
            for (int j = 0; j < ATT_; j++) {
                float kvj = kp[j];
                em += g_vnm[j] * tanha(qm[j] + kvj);
                ec += g_vnc[j] * tanha(qc[j] + kvj);
            }
            e = em + cm;
            c = ec + cc;
            p = 1.f / (1.f + __expf(-(e + nz)));
        }
        if (s == S_ - 1) p = 1.f;
        omp = 1.f - p;
        float x2f = omp;
        #pragma unroll
        for (int o = 1; o < 32; o <<= 1) {
            float y = __shfl_up_sync(0xffffffffu, x2f, o);
            if (lane >= o) x2f *= y;
        }
        if (lane == 31) wa[wid] = x2f;
        __syncthreads();
        if (wid == 0) {
            float a = wa[lane];
            #pragma unroll
            for (int o = 1; o < 32; o <<= 1) {
                float y = __shfl_up_sync(0xffffffffu, a, o);
                if (lane >= o) a *= y;
            }
            wa[lane] = a;
        }
        __syncthreads();
        float ip2 = wid ? x2f * wa[wid - 1] : x2f;
        smA[s] = ip2;
        __syncthreads();
    }

    const bool dead = (s > cut);
    smC[s] = c;

    float cp = s ? smA[s - 1] : 1.f;       // dead lanes: cp == 0 exactly
    float cpc = fminf(fmaxf(cp, 1e-20f), 1.f);
    float y2 = dead ? 0.f : (pv / s_psum) / cpc;

    float xs = y2;
    #pragma unroll
    for (int o = 1; o < 32; o <<= 1) {
        float y = __shfl_up_sync(0xffffffffu, xs, o);
        if (lane >= o) xs += y;
    }
    if (lane == 31) wc[wid] = xs;
    __syncthreads();                                        // B4
    if (wid == 0) {
        float a = wc[lane];
        #pragma unroll
        for (int o = 1; o < 32; o <<= 1) {
            float y = __shfl_up_sync(0xffffffffu, a, o);
            if (lane >= o) a += y;
        }
        wc[lane] = a;
    }
    __syncthreads();                                        // B5
    float cs = wid ? xs + wc[wid - 1] : xs;
    float alpha = p * cp * cs;              // dead -> p*0*cs = 0 exactly

    float mx = c;
    #pragma unroll
    for (int j = 1; j < W_; j++) { int i = s - j; if (i >= 0) mx = fmaxf(mx, smC[i]); }
    float eu = __expf(c - mx);              // <= 1, never inf
    smA[s] = eu;
    __syncthreads();                                        // B6

    float den = 0.f;
    #pragma unroll
    for (int j = 0; j < W_; j++) { int i = s - j; if (i >= 0) den += smA[i]; }
    den = fmaxf(den, 1e-10f);
    float g = dead ? 0.f : alpha / den;
    smC[s] = g;
    __syncthreads();                                        // B7

    float acc = 0.f;
    #pragma unroll
    for (int j = 0; j < W_; j++) { int i = s + j; if (i < S_) acc += smC[i]; }
    float beta = dead ? 0.f : eu * acc;
    smA[s] = beta;                          // safe: no smA reads after B7
    __syncthreads();                                        // B8

    // ------- fused context: this block owns batch b entirely -------
    int limit = cut + 1; if (limit > S_) limit = S_;   // live rows [0, limit)
    int d  = s & 511;                        // d-column
    int rg = s >> 9;                         // row-group 0/1
    const float* vb = value + ((size_t)b << 19) + d;   // value[b, 0, d]
    float a0 = 0.f, a1 = 0.f, a2 = 0.f, a3 = 0.f;
    int r = rg;
    for (; r + 6 < limit; r += 8) {
        a0 += smA[r]     * vb[(size_t)r << 9];
        a1 += smA[r + 2] * vb[(size_t)(r + 2) << 9];
        a2 += smA[r + 4] * vb[(size_t)(r + 4) << 9];
        a3 += smA[r + 6] * vb[(size_t)(r + 6) << 9];
    }
    for (; r < limit; r += 2) a0 += smA[r] * vb[(size_t)r << 9];
    float part = (a0 + a1) + (a2 + a3);
    if (rg == 1) smC[d] = part;              // safe: smC(g) reads ended at B8
    __syncthreads();                                        // B9
    if (rg == 0) out[b * 512 + d] = part + smC[d];
}

// ---------------- launch ------------------------------------------
extern "C" void kernel_launch(void* const* d_in, const int* in_sizes, int n_in,
                              void* d_out, int out_size) {
    const float* dec   = (const float*)d_in[0];
    const float* key   = (const float*)d_in[1];
    const float* value = (const float*)d_in[2];
    const float* prev  = (const float*)d_in[3];
    const float* noise = (const float*)d_in[4];
    const float* Wm    = (const float*)d_in[5];
    const float* bm    = (const float*)d_in[6];
    const float* vm    = (const float*)d_in[7];
    const float* gm    = (const float*)d_in[8];
    const float* vbm   = (const float*)d_in[9];
    const float* rm    = (const float*)d_in[10];
    const float* Wc    = (const float*)d_in[11];
    const float* bc    = (const float*)d_in[12];
    const float* vc    = (const float*)d_in[13];
    const float* gc    = (const float*)d_in[14];
    const float* vbc   = (const float*)d_in[15];
    const float* rc    = (const float*)d_in[16];
    float* out = (float*)d_out;

    k_pre<<<dim3(32, 3), 256>>>(dec, Wm, bm, Wc, bc, vm, gm, vc, gc);
    k_both<<<dim3(MONO_TILES_, B_), 256>>>(key, vbm, rm, vbc, rc);
    k_scan<<<B_, S_>>>(noise, prev, key, value, vbm, rm, vbc, rc, out);
}

// round 15
// speedup vs baseline: 1.9558x; 1.4024x over previous
#include <cuda_runtime.h>

#define B_   32
#define S_   1024
#define ATT_ 512
#define W_   8
#define MONO_S_ 384   // energies precomputed for s < MONO_S_
#define MONO_TILES_ 12

// ---------------- scratch (no allocations allowed) ----------------
__device__ float g_qbm[B_ * ATT_];   // dec_h @ Wm^T + bm
__device__ float g_qbc[B_ * ATT_];   // dec_h @ Wc^T + bc
__device__ float g_vnm[ATT_];        // gm * vm / ||vm||
__device__ float g_vnc[ATT_];
__device__ float g_me[B_ * S_];      // monotonic energy (s < MONO_S_)
__device__ float g_ce[B_ * S_];      // chunk energy    (s < MONO_S_)
__device__ float g_beta[B_ * S_];
__device__ int   g_cut[B_];          // per-batch active cutoff (inclusive)

__device__ __forceinline__ float tanha(float x) {
    float y;
    asm("tanh.approx.f32 %0, %1;" : "=f"(y) : "f"(x));
    return y;
}

// ---------------- K0: matvec + vnorm + zero (fused pre-pass) ------
// Matvec planes rebuilt for occupancy: warp-per-row, 8 rows/block,
// 64 blocks per matrix (128 total), ~40 regs -> multi-block residency.
__global__ void __launch_bounds__(256) k_pre(
        const float* __restrict__ dec,
        const float* __restrict__ Wm, const float* __restrict__ bm,
        const float* __restrict__ Wc, const float* __restrict__ bc,
        const float* __restrict__ vm, const float* __restrict__ gm,
        const float* __restrict__ vc, const float* __restrict__ gc,
        float* __restrict__ out) {
    int t = threadIdx.x;

    if (blockIdx.y == 2) {
        int x = blockIdx.x;
        if (x >= 32) return;
        out[x * 512 + t] = 0.f;
        out[x * 512 + 256 + t] = 0.f;
        if (x > 1) return;
        const float* v = x ? vc : vm;
        const float* g = x ? gc : gm;
        float* o       = x ? g_vnc : g_vnm;
        float x1 = v[t], x2 = v[t + 256];
        float ss = x1 * x1 + x2 * x2;
        __shared__ float red[8];
        #pragma unroll
        for (int off = 16; off; off >>= 1) ss += __shfl_down_sync(0xffffffffu, ss, off);
        if ((t & 31) == 0) red[t >> 5] = ss;
        __syncthreads();
        __shared__ float s_scale;
        if (t == 0) {
            float a = red[0] + red[1] + red[2] + red[3] + red[4] + red[5] + red[6] + red[7];
            s_scale = __ldg(g) / sqrtf(a);
        }
        __syncthreads();
        o[t] = x1 * s_scale;
        o[t + 256] = x2 * s_scale;
        return;
    }

    const float* W    = blockIdx.y ? Wc : Wm;
    const float* bias = blockIdx.y ? bc : bm;
    float* qout       = blockIdx.y ? g_qbc : g_qbm;

    int w = t >> 5, lane = t & 31;
    int row = blockIdx.x * 8 + w;                // warp-per-row, 64 blocks/matrix

    const float4* Wr = reinterpret_cast<const float4*>(W + (size_t)row * 512);
    float4 w0 = Wr[lane], w1 = Wr[lane + 32], w2 = Wr[lane + 64], w3 = Wr[lane + 96];
    float bias0 = bias[row];

    __shared__ float4 sdec[16 * 128];            // 32 KB: 16 batches
    const float4* dec4 = reinterpret_cast<const float4*>(dec);

    #pragma unroll
    for (int half = 0; half < 2; half++) {
        #pragma unroll
        for (int i = t; i < 2048; i += 256) sdec[i] = dec4[half * 2048 + i];
        __syncthreads();
        #pragma unroll 4
        for (int bb = 0; bb < 16; bb++) {
            int b = half * 16 + bb;
            float4 d0 = sdec[bb * 128 + lane];
            float4 d1 = sdec[bb * 128 + lane + 32];
            float4 d2 = sdec[bb * 128 + lane + 64];
            float4 d3 = sdec[bb * 128 + lane + 96];
            float a = w0.x * d0.x + w0.y * d0.y + w0.z * d0.z + w0.w * d0.w
                    + w1.x * d1.x + w1.y * d1.y + w1.z * d1.z + w1.w * d1.w
                    + w2.x * d2.x + w2.y * d2.y + w2.z * d2.z + w2.w * d2.w
                    + w3.x * d3.x + w3.y * d3.y + w3.z * d3.z + w3.w * d3.w;
            #pragma unroll
            for (int off = 16; off; off >>= 1)
                a += __shfl_down_sync(0xffffffffu, a, off);
            if (lane == 0) qout[b * ATT_ + row] = a + bias0;
        }
        __syncthreads();
    }
}

// ---------------- K1: both energies for s < MONO_S_ (one key pass) -
__global__ void __launch_bounds__(256) k_both(
        const float* __restrict__ key,
        const float* __restrict__ vbm, const float* __restrict__ rm,
        const float* __restrict__ vbc, const float* __restrict__ rc) {
    int b = blockIdx.y;
    int tile = blockIdx.x;
    int t = threadIdx.x, w = t >> 5, lane = t & 31;

    __shared__ float sq[2048];   // [qm 512 | qc 512 | vm 512 | vc 512]
    {
        const float4* qm4 = reinterpret_cast<const float4*>(g_qbm + b * ATT_);
        const float4* qc4 = reinterpret_cast<const float4*>(g_qbc + b * ATT_);
        const float4* vm4 = reinterpret_cast<const float4*>(g_vnm);
        const float4* vc4 = reinterpret_cast<const float4*>(g_vnc);
        float4* s4 = reinterpret_cast<float4*>(sq);
        if (t < 128) {
            s4[t]       = qm4[t];
            s4[256 + t] = vm4[t];
        } else {
            int u = t - 128;
            s4[128 + u] = qc4[u];
            s4[384 + u] = vc4[u];
        }
    }
    __syncthreads();

    const float cm = __ldg(vbm) + __ldg(rm);
    const float cc = __ldg(vbc) + __ldg(rc);

    int s0 = tile * 32 + w * 4;
    #pragma unroll
    for (int r = 0; r < 4; r++) {
        int s = s0 + r;
        const float* kp = key + (((size_t)b * S_ + s) << 9);
        float kv[16];
        #pragma unroll
        for (int j = 0; j < 16; j++) kv[j] = kp[lane + 32 * j];
        float em = 0.f, ec = 0.f;
        #pragma unroll
        for (int j = 0; j < 16; j++) {
            int idx = lane + 32 * j;
            em += sq[1024 + idx] * tanha(sq[idx] + kv[j]);
            ec += sq[1536 + idx] * tanha(sq[512 + idx] + kv[j]);
        }
        #pragma unroll
        for (int off = 16; off; off >>= 1) {
            em += __shfl_down_sync(0xffffffffu, em, off);
            ec += __shfl_down_sync(0xffffffffu, ec, off);
        }
        if (lane == 0) {
            g_me[b * S_ + s] = em + cm;
            g_ce[b * S_ + s] = ec + cc;
        }
    }
}

// ---------------- K2: fused cutoff + scans + windows -> beta -------
__global__ void __launch_bounds__(1024) k_scan(
        const float* __restrict__ noise, const float* __restrict__ prev,
        const float* __restrict__ key,
        const float* __restrict__ vbm, const float* __restrict__ rm,
        const float* __restrict__ vbc, const float* __restrict__ rc) {
    int b = blockIdx.x, s = threadIdx.x;   // 1024 threads
    int lane = s & 31, wid = s >> 5;
    const int base = b * S_;
    __shared__ float smA[S_];
    __shared__ float smC[S_];
    __shared__ float wa[32], wb[32], wc[32];
    __shared__ int   s_wf[MONO_TILES_];
    __shared__ float s_psum;

    bool head = (s < MONO_S_);
    float e  = head ? g_me[base + s] : 0.f;
    float c  = head ? g_ce[base + s] : 0.f;
    float nz = noise[base + s];
    float pv = prev[base + s];

    float p = 1.f / (1.f + __expf(-(e + nz)));
    float omp = head ? (1.f - p) : 1.f;

    float x = omp;
    #pragma unroll
    for (int o = 1; o < 32; o <<= 1) {
        float y = __shfl_up_sync(0xffffffffu, x, o);
        if (lane >= o) x *= y;
    }
    if (lane == 31) wa[wid] = x;
    float ts = pv;
    #pragma unroll
    for (int off = 16; off; off >>= 1) ts += __shfl_down_sync(0xffffffffu, ts, off);
    if (lane == 0) wb[wid] = ts;
    __syncthreads();                                        // B1

    if (wid == 0) {
        float a = wa[lane];
        #pragma unroll
        for (int o = 1; o < 32; o <<= 1) {
            float y = __shfl_up_sync(0xffffffffu, a, o);
            if (lane >= o) a *= y;
        }
        wa[lane] = a;
    } else if (wid == 1) {
        float a = wb[lane];
        #pragma unroll
        for (int off = 16; off; off >>= 1) a += __shfl_down_sync(0xffffffffu, a, off);
        if (lane == 0) s_psum = a;
    }
    __syncthreads();                                        // B2

    float ip = wid ? x * wa[wid - 1] : x;
    unsigned zb = __ballot_sync(0xffffffffu, ip == 0.f);
    if (wid < MONO_TILES_ && lane == 0)
        s_wf[wid] = zb ? (wid * 32 + __ffs(zb) - 1) : 0x7fffffff;
    smA[s] = ip;
    __syncthreads();                                        // B3

    int Z = 0x7fffffff;
    #pragma unroll
    for (int i = 0; i < MONO_TILES_; i++) Z = min(Z, s_wf[i]);
    const int cut = (Z <= MONO_S_ - 33) ? Z + 32 : 1024;
    if (s == 0) g_cut[b] = cut;

    if (cut >= 1024) {
        // rare fallback: compute tail energies, redo the product scan
        if (!head) {
            const float cm = __ldg(vbm) + __ldg(rm);
            const float cc = __ldg(vbc) + __ldg(rc);
            const float* kp = key + (((size_t)base + s) << 9);
            const float* qm = g_qbm + b * ATT_;
            const float* qc = g_qbc + b * ATT_;
            float em = 0.f, ec = 0.f;
            for (int j = 0; j < ATT_; j++) {
                float kvj = kp[j];
                em += g_vnm[j] * tanha(qm[j] + kvj);
                ec += g_vnc[j] * tanha(qc[j] + kvj);
            }
            e = em + cm;
            c = ec + cc;
            p = 1.f / (1.f + __expf(-(e + nz)));
        }
        if (s == S_ - 1) p = 1.f;
        omp = 1.f - p;
        float x2f = omp;
        #pragma unroll
        for (int o = 1; o < 32; o <<= 1) {
            float y = __shfl_up_sync(0xffffffffu, x2f, o);
            if (lane >= o) x2f *= y;
        }
        if (lane == 31) wa[wid] = x2f;
        __syncthreads();
        if (wid == 0) {
            float a = wa[lane];
            #pragma unroll
            for (int o = 1; o < 32; o <<= 1) {
                float y = __shfl_up_sync(0xffffffffu, a, o);
                if (lane >= o) a *= y;
            }
            wa[lane] = a;
        }
        __syncthreads();
        float ip2 = wid ? x2f * wa[wid - 1] : x2f;
        smA[s] = ip2;
        __syncthreads();
    }

    const bool dead = (s > cut);
    smC[s] = c;

    float cp = s ? smA[s - 1] : 1.f;       // dead lanes: cp == 0 exactly
    float cpc = fminf(fmaxf(cp, 1e-20f), 1.f);
    float y2 = dead ? 0.f : (pv / s_psum) / cpc;

    float xs = y2;
    #pragma unroll
    for (int o = 1; o < 32; o <<= 1) {
        float y = __shfl_up_sync(0xffffffffu, xs, o);
        if (lane >= o) xs += y;
    }
    if (lane == 31) wc[wid] = xs;
    __syncthreads();                                        // B4
    if (wid == 0) {
        float a = wc[lane];
        #pragma unroll
        for (int o = 1; o < 32; o <<= 1) {
            float y = __shfl_up_sync(0xffffffffu, a, o);
            if (lane >= o) a += y;
        }
        wc[lane] = a;
    }
    __syncthreads();                                        // B5
    float cs = wid ? xs + wc[wid - 1] : xs;
    float alpha = p * cp * cs;              // dead -> p*0*cs = 0 exactly

    float mx = c;
    #pragma unroll
    for (int j = 1; j < W_; j++) { int i = s - j; if (i >= 0) mx = fmaxf(mx, smC[i]); }
    float eu = __expf(c - mx);              // <= 1, never inf
    smA[s] = eu;
    __syncthreads();                                        // B6

    float den = 0.f;
    #pragma unroll
    for (int j = 0; j < W_; j++) { int i = s - j; if (i >= 0) den += smA[i]; }
    den = fmaxf(den, 1e-10f);
    float g = dead ? 0.f : alpha / den;
    smC[s] = g;
    __syncthreads();                                        // B7

    float acc = 0.f;
    #pragma unroll
    for (int j = 0; j < W_; j++) { int i = s + j; if (i < S_) acc += smC[i]; }
    g_beta[base + s] = dead ? 0.f : eu * acc;
}

// ---------------- K3: context = beta . value ----------------------
#define SCHUNK_ 16
#define NCHUNK_LIVE_ 24
__global__ void __launch_bounds__(256) k_ctx(const float* __restrict__ value,
                                             float* __restrict__ out) {
    int b = blockIdx.y;
    int cut = g_cut[b];
    int t = threadIdx.x;
    __shared__ float sb[SCHUNK_];

    for (int sc = blockIdx.x; sc < S_ / SCHUNK_; sc += NCHUNK_LIVE_) {
        if (sc * SCHUNK_ > cut) return;      // beta exactly 0 beyond cut
        if (t < SCHUNK_) sb[t] = g_beta[b * S_ + sc * SCHUNK_ + t];
        __syncthreads();
        const float* vp = value + (((size_t)b * S_ + sc * SCHUNK_) << 9);
        float a0 = 0.f, a1 = 0.f;
        #pragma unroll
        for (int s = 0; s < SCHUNK_; s++) {
            float bs = sb[s];
            a0 += bs * vp[(s << 9) + t];
            a1 += bs * vp[(s << 9) + t + 256];
        }
        atomicAdd(out + b * 512 + t,       a0);
        atomicAdd(out + b * 512 + t + 256, a1);
        __syncthreads();
    }
}

// ---------------- launch ------------------------------------------
extern "C" void kernel_launch(void* const* d_in, const int* in_sizes, int n_in,
                              void* d_out, int out_size) {
    const float* dec   = (const float*)d_in[0];
    const float* key   = (const float*)d_in[1];
    const float* value = (const float*)d_in[2];
    const float* prev  = (const float*)d_in[3];
    const float* noise = (const float*)d_in[4];
    const float* Wm    = (const float*)d_in[5];
    const float* bm    = (const float*)d_in[6];
    const float* vm    = (const float*)d_in[7];
    const float* gm    = (const float*)d_in[8];
    const float* vbm   = (const float*)d_in[9];
    const float* rm    = (const float*)d_in[10];
    const float* Wc    = (const float*)d_in[11];
    const float* bc    = (const float*)d_in[12];
    const float* vc    = (const float*)d_in[13];
    const float* gc    = (const float*)d_in[14];
    const float* vbc   = (const float*)d_in[15];
    const float* rc    = (const float*)d_in[16];
    float* out = (float*)d_out;

    k_pre<<<dim3(64, 3), 256>>>(dec, Wm, bm, Wc, bc, vm, gm, vc, gc, out);
    k_both<<<dim3(MONO_TILES_, B_), 256>>>(key, vbm, rm, vbc, rc);
    k_scan<<<B_, S_>>>(noise, prev, key, vbm, rm, vbc, rc);
    k_ctx<<<dim3(NCHUNK_LIVE_, B_), 256>>>(value, out);
}